// round 15
// baseline (speedup 1.0000x reference)
#include <cuda_runtime.h>
#include <cuda_fp16.h>
#include <math_constants.h>

// Problem constants (shapes fixed by the reference)
constexpr int NCH   = 32;     // n channels
constexpr int KNB   = 32;     // K neighbours
constexpr int MCL   = 16;     // M clusters
constexpr float MU_C = 1.0f;
constexpr int NMAX  = 131072; // scratch upper bound for N
constexpr int PB_BLOCKS = 296;   // 2 blocks/SM
constexpr int PC_BLOCKS = 444;   // 3 blocks/SM, 256 thr

// ---- device scratch (no allocations allowed) ----
static __device__ float   g_encpart[16 * NCH];            // per-chunk partial dots for encoded
static __device__ float   g_encoded[NCH];                 // encoded vector
static __device__ float   g_a[MCL * NCH];                 // a[m][i] = 1/(bw[i,m]*MU)^2
static __device__ __half2 g_dect2[(size_t)NMAX * (NCH/2)];// dec_t[p][i] = half(decoder[i][p]*encoded[i])
static __device__ float   g_Spart[PB_BLOCKS * NCH * KNB]; // per-block partial S, layout [block][k][i]
static __device__ float   g_invS[KNB * NCH];              // invS[k][i]

// ------------------------------------------------------------------
// Kernel A: partial dot products for encoded[i] = enc_w[i,:] . x
// ------------------------------------------------------------------
__global__ void kA_encoded(const float* __restrict__ enc_w,
                           const float* __restrict__ x, int N) {
    int c = blockIdx.x;   // chunk
    int r = blockIdx.y;   // row (channel)
    int chunk = 4 * ((N + 63) / 64);      // 16 chunks of 4-aligned size
    int p0 = c * chunk;
    int p1 = min(p0 + chunk, N);

    const float* __restrict__ row = enc_w + (size_t)r * N;
    float s = 0.0f;
    int nv4 = (p1 - p0) / 4;              // p0 is 4-aligned
    const float4* __restrict__ row4 = reinterpret_cast<const float4*>(row + p0);
    const float4* __restrict__ x4   = reinterpret_cast<const float4*>(x + p0);
    for (int q = threadIdx.x; q < nv4; q += blockDim.x) {
        float4 a = row4[q], b = x4[q];
        s += a.x * b.x + a.y * b.y + a.z * b.z + a.w * b.w;
    }
    for (int p = p0 + 4 * nv4 + threadIdx.x; p < p1; p += blockDim.x)
        s += row[p] * x[p];

    #pragma unroll
    for (int o = 16; o > 0; o >>= 1)
        s += __shfl_xor_sync(0xffffffffu, s, o);

    __shared__ float ws[8];
    int lane = threadIdx.x & 31, wid = threadIdx.x >> 5;
    if (lane == 0) ws[wid] = s;
    __syncthreads();
    if (threadIdx.x == 0) {
        float t = 0.0f;
        #pragma unroll
        for (int w = 0; w < 8; w++) t += ws[w];
        g_encpart[c * NCH + r] = t;
    }
}

// ------------------------------------------------------------------
// Kernel B: reduce encoded partials, compute bandwidths -> a[m][i]
// ------------------------------------------------------------------
__global__ void kB_bandwidths(const float* __restrict__ bw_w,
                              const float* __restrict__ bw_b,
                              const float* __restrict__ enc_b) {
    __shared__ float enc_s[NCH];
    int t = threadIdx.x;
    if (t < NCH) {
        float s = enc_b[t];
        #pragma unroll
        for (int c = 0; c < 16; c++) s += g_encpart[c * NCH + t];
        enc_s[t] = s;
        g_encoded[t] = s;
    }
    __syncthreads();

    float s = bw_b[t];
    const float* __restrict__ wrow = bw_w + (size_t)t * NCH;
    #pragma unroll
    for (int q = 0; q < NCH; q++) s += wrow[q] * enc_s[q];
    float w = s * MU_C;
    int i = t / MCL, m = t % MCL;
    g_a[m * NCH + i] = 1.0f / (w * w);
}

// ------------------------------------------------------------------
// Kernel T: transposed + encoded-folded decoder, stored fp16
// ------------------------------------------------------------------
__global__ void kT_transpose(const float* __restrict__ decoder, int N) {
    __shared__ float enc_s[NCH];
    if (threadIdx.x < NCH) enc_s[threadIdx.x] = g_encoded[threadIdx.x];
    __syncthreads();

    int p = blockIdx.x * blockDim.x + threadIdx.x;
    if (p >= N) return;

    __half2 h[NCH / 2];
    #pragma unroll
    for (int q = 0; q < NCH / 2; q++) {
        float v0 = decoder[(size_t)(2 * q)     * N + p] * enc_s[2 * q];
        float v1 = decoder[(size_t)(2 * q + 1) * N + p] * enc_s[2 * q + 1];
        h[q] = __floats2half2_rn(v0, v1);
    }
    uint4* dst = reinterpret_cast<uint4*>(g_dect2 + (size_t)p * (NCH / 2));
    const uint4* src = reinterpret_cast<const uint4*>(h);
    #pragma unroll
    for (int q = 0; q < 4; q++) dst[q] = src[q];
}

// ------------------------------------------------------------------
// Kernel PB v5: S[i,k] = sum_j relu(1 - d[j,k]^2 * a[i, lab_j])
// Packed fma.rn.f32x2 window math. (unchanged — 18.4us, 69% issue)
// ------------------------------------------------------------------
__global__ void __launch_bounds__(512, 2) kPB_sums(
        const float* __restrict__ nd, const int* __restrict__ labels, int N) {
    __shared__ float a_s[MCL * NCH];
    __shared__ float S_sm[KNB * NCH];
    __shared__ __align__(16) float d2w[16][4][KNB];   // [warp][jj][k] = -d^2
    int t = threadIdx.x;
    if (t < MCL * NCH) a_s[t] = g_a[t];
    for (int u = t; u < KNB * NCH; u += 512) S_sm[u] = 0.0f;
    __syncthreads();

    int lane = t & 31, wid = t >> 5;       // 16 warps
    int gw = blockIdx.x * 16 + wid;
    int nwj = gridDim.x * 16 * 4;          // j stride (4 j per warp per stage)

    unsigned long long one2;
    asm("mov.b64 %0, {%1, %1};" : "=l"(one2) : "f"(1.0f));

    float acc[KNB];
    #pragma unroll
    for (int k = 0; k < KNB; k++) acc[k] = 0.0f;

    for (int jb = gw * 4; jb < N; jb += nwj) {
        float nd2v[4];
        int   labv[4];
        #pragma unroll
        for (int u = 0; u < 4; u++) {
            int j = jb + u;
            bool ok = (j < N);
            float dd = ok ? nd[(size_t)j * KNB + lane] : 0.0f;
            nd2v[u] = ok ? (-dd * dd) : -CUDART_INF_F;
            labv[u] = ok ? labels[j] : 0;
        }
        __syncwarp();                       // WAR: prior reads done
        #pragma unroll
        for (int u = 0; u < 4; u++) d2w[wid][u][lane] = nd2v[u];
        __syncwarp();                       // RAW: stores visible

        #pragma unroll
        for (int u = 0; u < 4; u++) {
            float a = a_s[labv[u] * NCH + lane];   // lane = channel i
            unsigned long long a2;
            asm("mov.b64 %0, {%1, %1};" : "=l"(a2) : "f"(a));
            unsigned sbase = (unsigned)__cvta_generic_to_shared(&d2w[wid][u][0]);
            #pragma unroll
            for (int kq = 0; kq < KNB / 4; kq++) {
                unsigned long long q0, q1, w0, w1;
                asm volatile("ld.shared.v2.u64 {%0, %1}, [%2];"
                             : "=l"(q0), "=l"(q1) : "r"(sbase + 16u * kq));
                asm("fma.rn.f32x2 %0, %1, %2, %3;" : "=l"(w0) : "l"(q0), "l"(a2), "l"(one2));
                asm("fma.rn.f32x2 %0, %1, %2, %3;" : "=l"(w1) : "l"(q1), "l"(a2), "l"(one2));
                float f0, f1, f2, f3;
                asm("mov.b64 {%0, %1}, %2;" : "=f"(f0), "=f"(f1) : "l"(w0));
                asm("mov.b64 {%0, %1}, %2;" : "=f"(f2), "=f"(f3) : "l"(w1));
                acc[4 * kq + 0] += fmaxf(f0, 0.0f);
                acc[4 * kq + 1] += fmaxf(f1, 0.0f);
                acc[4 * kq + 2] += fmaxf(f2, 0.0f);
                acc[4 * kq + 3] += fmaxf(f3, 0.0f);
            }
        }
    }

    #pragma unroll
    for (int k = 0; k < KNB; k++)
        atomicAdd(&S_sm[k * NCH + lane], acc[k]);
    __syncthreads();

    for (int u = t; u < KNB * NCH; u += 512)
        g_Spart[blockIdx.x * (KNB * NCH) + u] = S_sm[u];
}

// ------------------------------------------------------------------
// Kernel PF: finalize invS[k][i] = 1 / sum_b Spart[b][k][i]
// ------------------------------------------------------------------
__global__ void kPF_finalize(int nblocks) {
    int u = blockIdx.x * 128 + threadIdx.x;
    float s0 = 0.0f, s1 = 0.0f, s2 = 0.0f, s3 = 0.0f;
    int b = 0;
    for (; b + 3 < nblocks; b += 4) {
        s0 += g_Spart[(b + 0) * (KNB * NCH) + u];
        s1 += g_Spart[(b + 1) * (KNB * NCH) + u];
        s2 += g_Spart[(b + 2) * (KNB * NCH) + u];
        s3 += g_Spart[(b + 3) * (KNB * NCH) + u];
    }
    for (; b < nblocks; b++) s0 += g_Spart[b * (KNB * NCH) + u];
    g_invS[u] = 1.0f / (s0 + s1 + s2 + s3);
}

// ------------------------------------------------------------------
// Kernel PC v8: out[j] = sum_k sum_i dec_t[id_jk][i] * win * invS[k][i]
// WARP-PER-POINT, lane = channel.
//  - invS lives in 32 REGISTERS per lane (loaded once per warp)
//  - gathers are LDG.U16 (1 row = 1 line-touch per instruction)
//  - d2+id interleaved in smem: 1 LDS.128 per k-pair
//  - 4-kp-deep gather ring (8 LDGs in flight)
// __launch_bounds__(256,3): 85-reg cap -> no spill possible.
// ------------------------------------------------------------------
__global__ void __launch_bounds__(256, 3) kPC_output(
        const float* __restrict__ nd, const int* __restrict__ nid,
        const int* __restrict__ labels, float* __restrict__ out, int N) {
    __shared__ __align__(16) float a_s[MCL][NCH];   // [lab][ch]
    __shared__ __align__(16) uint2 stage[8][KNB];   // [wid][k] = {d2 bits, id}

    int t = threadIdx.x;
    int lane = t & 31, wid = t >> 5;     // 8 warps

    for (int u = t; u < MCL * NCH; u += 256)
        a_s[u / NCH][u % NCH] = g_a[u];
    __syncthreads();

    // invS for MY channel, all 32 k -> registers (once per warp lifetime)
    float ivr[KNB];
    #pragma unroll
    for (int k = 0; k < KNB; k++) ivr[k] = g_invS[k * NCH + lane];

    const __half* __restrict__ gh = reinterpret_cast<const __half*>(g_dect2) + lane;

    int nw = gridDim.x * 8;
    for (int j = blockIdx.x * 8 + wid; j < N; j += nw) {
        // coalesced per-point loads (one 128B line each)
        float dd = nd[(unsigned)j * 32u + lane];
        int   id = nid[(unsigned)j * 32u + lane];
        int   lab = labels[j];
        float a = a_s[lab][lane];

        __syncwarp();                     // WAR vs previous point's reads
        stage[wid][lane] = make_uint2(__float_as_uint(dd * dd), (unsigned)id);
        __syncwarp();                     // RAW: stores visible

        // ---- prologue: read kp=0..3 stage, issue 8 gathers ----
        float2 d2q[4];
        __half vh[4][2];
        #pragma unroll
        for (int q = 0; q < 4; q++) {
            uint4 s = *reinterpret_cast<const uint4*>(&stage[wid][2 * q]);
            d2q[q] = make_float2(__uint_as_float(s.x), __uint_as_float(s.z));
            vh[q][0] = gh[s.y * 32u];
            vh[q][1] = gh[s.w * 32u];
        }

        float acc0 = 0.0f, acc1 = 0.0f;
        #pragma unroll
        for (int kp = 0; kp < 16; kp++) {
            int sl = kp & 3;
            float v0 = __half2float(vh[sl][0]);
            float v1 = __half2float(vh[sl][1]);
            float w0 = fmaxf(fmaf(-d2q[sl].x, a, 1.0f), 0.0f);
            float w1 = fmaxf(fmaf(-d2q[sl].y, a, 1.0f), 0.0f);

            if (kp + 4 < 16) {            // refill ring slot for kp+4
                uint4 s = *reinterpret_cast<const uint4*>(&stage[wid][2 * (kp + 4)]);
                d2q[sl] = make_float2(__uint_as_float(s.x), __uint_as_float(s.z));
                vh[sl][0] = gh[s.y * 32u];
                vh[sl][1] = gh[s.w * 32u];
            }

            acc0 = fmaf(v0 * w0, ivr[2 * kp],     acc0);
            acc1 = fmaf(v1 * w1, ivr[2 * kp + 1], acc1);
        }

        float s = acc0 + acc1;
        #pragma unroll
        for (int o = 16; o > 0; o >>= 1)
            s += __shfl_xor_sync(0xffffffffu, s, o);
        if (lane == 0) out[j] = s;
    }
}

// ------------------------------------------------------------------
extern "C" void kernel_launch(void* const* d_in, const int* in_sizes, int n_in,
                              void* d_out, int out_size) {
    const float* x       = (const float*)d_in[0];
    const float* enc_w   = (const float*)d_in[1];
    const float* enc_b   = (const float*)d_in[2];
    const float* decoder = (const float*)d_in[3];
    const float* bw_w    = (const float*)d_in[4];
    const float* bw_b    = (const float*)d_in[5];
    const float* nd      = (const float*)d_in[6];
    const int*   nid     = (const int*)d_in[7];
    const int*   labels  = (const int*)d_in[8];
    float* out = (float*)d_out;
    int N = in_sizes[0];

    kA_encoded<<<dim3(16, NCH), 256>>>(enc_w, x, N);
    kB_bandwidths<<<1, NCH * MCL>>>(bw_w, bw_b, enc_b);
    kT_transpose<<<(N + 255) / 256, 256>>>(decoder, N);
    kPB_sums<<<PB_BLOCKS, 512>>>(nd, labels, N);
    kPF_finalize<<<8, 128>>>(PB_BLOCKS);
    kPC_output<<<PC_BLOCKS, 256>>>(nd, nid, labels, out, N);
}

// round 16
// speedup vs baseline: 1.3760x; 1.3760x over previous
#include <cuda_runtime.h>
#include <cuda_fp16.h>
#include <math_constants.h>

// Problem constants (shapes fixed by the reference)
constexpr int NCH   = 32;     // n channels
constexpr int KNB   = 32;     // K neighbours
constexpr int MCL   = 16;     // M clusters
constexpr float MU_C = 1.0f;
constexpr int NMAX  = 131072; // scratch upper bound for N
constexpr int PB_BLOCKS = 296;   // kPB part: 2 blocks/SM
constexpr int KT_BLOCKS = 196;   // kT part: ceil(100000/512)

// ---- device scratch (no allocations allowed) ----
static __device__ float   g_encpart[16 * NCH];            // per-chunk partial dots for encoded
static __device__ float   g_encoded[NCH];                 // encoded vector
static __device__ float   g_a[MCL * NCH];                 // a[m][i] = 1/(bw[i,m]*MU)^2
static __device__ __half2 g_dect2[(size_t)NMAX * (NCH/2)];// dec_t[p][i] = half(decoder[i][p]*encoded[i])
static __device__ float   g_S[KNB * NCH];                 // S[k][i], atomically accumulated

// ------------------------------------------------------------------
// Kernel A: partial dot products for encoded[i] = enc_w[i,:] . x
// ------------------------------------------------------------------
__global__ void kA_encoded(const float* __restrict__ enc_w,
                           const float* __restrict__ x, int N) {
    int c = blockIdx.x;   // chunk
    int r = blockIdx.y;   // row (channel)
    int chunk = 4 * ((N + 63) / 64);      // 16 chunks of 4-aligned size
    int p0 = c * chunk;
    int p1 = min(p0 + chunk, N);

    const float* __restrict__ row = enc_w + (size_t)r * N;
    float s = 0.0f;
    int nv4 = (p1 - p0) / 4;              // p0 is 4-aligned
    const float4* __restrict__ row4 = reinterpret_cast<const float4*>(row + p0);
    const float4* __restrict__ x4   = reinterpret_cast<const float4*>(x + p0);
    for (int q = threadIdx.x; q < nv4; q += blockDim.x) {
        float4 a = row4[q], b = x4[q];
        s += a.x * b.x + a.y * b.y + a.z * b.z + a.w * b.w;
    }
    for (int p = p0 + 4 * nv4 + threadIdx.x; p < p1; p += blockDim.x)
        s += row[p] * x[p];

    #pragma unroll
    for (int o = 16; o > 0; o >>= 1)
        s += __shfl_xor_sync(0xffffffffu, s, o);

    __shared__ float ws[8];
    int lane = threadIdx.x & 31, wid = threadIdx.x >> 5;
    if (lane == 0) ws[wid] = s;
    __syncthreads();
    if (threadIdx.x == 0) {
        float t = 0.0f;
        #pragma unroll
        for (int w = 0; w < 8; w++) t += ws[w];
        g_encpart[c * NCH + r] = t;
    }
}

// ------------------------------------------------------------------
// Kernel B: reduce encoded partials, compute bandwidths -> a[m][i].
// Also zeroes g_S for this replay (runs before the fused kTB kernel).
// ------------------------------------------------------------------
__global__ void kB_bandwidths(const float* __restrict__ bw_w,
                              const float* __restrict__ bw_b,
                              const float* __restrict__ enc_b) {
    __shared__ float enc_s[NCH];
    int t = threadIdx.x;
    // zero the S accumulator (1024 floats, 512 threads)
    g_S[t] = 0.0f;
    g_S[t + 512] = 0.0f;

    if (t < NCH) {
        float s = enc_b[t];
        #pragma unroll
        for (int c = 0; c < 16; c++) s += g_encpart[c * NCH + t];
        enc_s[t] = s;
        g_encoded[t] = s;
    }
    __syncthreads();

    float s = bw_b[t];
    const float* __restrict__ wrow = bw_w + (size_t)t * NCH;
    #pragma unroll
    for (int q = 0; q < NCH; q++) s += wrow[q] * enc_s[q];
    float w = s * MU_C;
    int i = t / MCL, m = t % MCL;
    g_a[m * NCH + i] = 1.0f / (w * w);
}

// ------------------------------------------------------------------
// Fused kernel TB: blocks [0, KT_BLOCKS) run the decoder transpose,
// blocks [KT_BLOCKS, KT_BLOCKS+PB_BLOCKS) run the window-sum pass.
// Both depend only on kB outputs -> they run CONCURRENTLY.
// ------------------------------------------------------------------
__global__ void __launch_bounds__(512, 2) kTB_fused(
        const float* __restrict__ decoder,
        const float* __restrict__ nd, const int* __restrict__ labels, int N) {
    int t = threadIdx.x;

    if (blockIdx.x < KT_BLOCKS) {
        // ================= kT: transposed + encoded-folded decoder =========
        __shared__ float enc_s[NCH];
        if (t < NCH) enc_s[t] = g_encoded[t];
        __syncthreads();

        int p = blockIdx.x * 512 + t;
        if (p >= N) return;

        __half2 h[NCH / 2];
        #pragma unroll
        for (int q = 0; q < NCH / 2; q++) {
            float v0 = decoder[(size_t)(2 * q)     * N + p] * enc_s[2 * q];
            float v1 = decoder[(size_t)(2 * q + 1) * N + p] * enc_s[2 * q + 1];
            h[q] = __floats2half2_rn(v0, v1);
        }
        uint4* dst = reinterpret_cast<uint4*>(g_dect2 + (size_t)p * (NCH / 2));
        const uint4* src = reinterpret_cast<const uint4*>(h);
        #pragma unroll
        for (int q = 0; q < 4; q++) dst[q] = src[q];
        return;
    }

    // ================= kPB: S[i,k] = sum_j relu(1 - d^2 * a) =============
    int pbid = blockIdx.x - KT_BLOCKS;      // 0..PB_BLOCKS-1

    __shared__ float a_s[MCL * NCH];
    __shared__ float S_sm[KNB * NCH];
    __shared__ __align__(16) float d2w[16][4][KNB];   // [warp][jj][k] = -d^2
    if (t < MCL * NCH) a_s[t] = g_a[t];
    for (int u = t; u < KNB * NCH; u += 512) S_sm[u] = 0.0f;
    __syncthreads();

    int lane = t & 31, wid = t >> 5;       // 16 warps
    int gw = pbid * 16 + wid;
    int nwj = PB_BLOCKS * 16 * 4;          // j stride (4 j per warp per stage)

    unsigned long long one2;
    asm("mov.b64 %0, {%1, %1};" : "=l"(one2) : "f"(1.0f));

    float acc[KNB];
    #pragma unroll
    for (int k = 0; k < KNB; k++) acc[k] = 0.0f;

    for (int jb = gw * 4; jb < N; jb += nwj) {
        float nd2v[4];
        int   labv[4];
        #pragma unroll
        for (int u = 0; u < 4; u++) {
            int j = jb + u;
            bool ok = (j < N);
            float dd = ok ? nd[(size_t)j * KNB + lane] : 0.0f;
            nd2v[u] = ok ? (-dd * dd) : -CUDART_INF_F;
            labv[u] = ok ? labels[j] : 0;
        }
        __syncwarp();                       // WAR: prior reads done
        #pragma unroll
        for (int u = 0; u < 4; u++) d2w[wid][u][lane] = nd2v[u];
        __syncwarp();                       // RAW: stores visible

        #pragma unroll
        for (int u = 0; u < 4; u++) {
            float a = a_s[labv[u] * NCH + lane];   // lane = channel i
            unsigned long long a2;
            asm("mov.b64 %0, {%1, %1};" : "=l"(a2) : "f"(a));
            unsigned sbase = (unsigned)__cvta_generic_to_shared(&d2w[wid][u][0]);
            #pragma unroll
            for (int kq = 0; kq < KNB / 4; kq++) {
                unsigned long long q0, q1, w0, w1;
                asm volatile("ld.shared.v2.u64 {%0, %1}, [%2];"
                             : "=l"(q0), "=l"(q1) : "r"(sbase + 16u * kq));
                asm("fma.rn.f32x2 %0, %1, %2, %3;" : "=l"(w0) : "l"(q0), "l"(a2), "l"(one2));
                asm("fma.rn.f32x2 %0, %1, %2, %3;" : "=l"(w1) : "l"(q1), "l"(a2), "l"(one2));
                float f0, f1, f2, f3;
                asm("mov.b64 {%0, %1}, %2;" : "=f"(f0), "=f"(f1) : "l"(w0));
                asm("mov.b64 {%0, %1}, %2;" : "=f"(f2), "=f"(f3) : "l"(w1));
                acc[4 * kq + 0] += fmaxf(f0, 0.0f);
                acc[4 * kq + 1] += fmaxf(f1, 0.0f);
                acc[4 * kq + 2] += fmaxf(f2, 0.0f);
                acc[4 * kq + 3] += fmaxf(f3, 0.0f);
            }
        }
    }

    #pragma unroll
    for (int k = 0; k < KNB; k++)
        atomicAdd(&S_sm[k * NCH + lane], acc[k]);
    __syncthreads();

    // spread-address global accumulation (REDG, no return)
    for (int u = t; u < KNB * NCH; u += 512)
        atomicAdd(&g_S[u], S_sm[u]);
}

// ------------------------------------------------------------------
// Kernel PC (R12 v5 — best measured): out[j] = sum_{k,i} dec_t*win*invS
// warp = 4 points (8 lanes each), lane = channel QUAD, LDG.64 gathers,
// 2-slot gather ring. invS computed inline (1/g_S) during smem fill.
// ------------------------------------------------------------------
__global__ void __launch_bounds__(512, 2) kPC_output(
        const float4* __restrict__ nd4, const int4* __restrict__ nid4,
        const int* __restrict__ labels, float* __restrict__ out, int N) {
    __shared__ __align__(16) float a_s[MCL][NCH];      // [lab][ch]
    __shared__ __align__(16) float ivs_s[KNB][8][4];   // [k][chquad][4]
    __shared__ __align__(16) float d2_sm[16][4][KNB];  // [wid][jj][k] = d^2
    __shared__ __align__(16) int   id_sm[16][4][KNB];  // [wid][jj][k]

    int t = threadIdx.x;
    for (int u = t; u < MCL * NCH; u += 512)
        a_s[u / NCH][u % NCH] = g_a[u];
    for (int u = t; u < KNB * NCH; u += 512) {
        int k = u / NCH, i = u % NCH;
        ivs_s[k][i >> 2][i & 3] = 1.0f / g_S[u];
    }
    __syncthreads();

    int lane = t & 31, wid = t >> 5;     // 16 warps
    int jj   = lane >> 3;                // which of 4 points
    int sub  = lane & 7;                 // channel quad (channels 4sub..4sub+3)

    const uint2* __restrict__ gb = reinterpret_cast<const uint2*>(g_dect2) + sub;

    int P  = (N + 3) >> 2;               // number of j-quads
    int nw = gridDim.x * 16;

    for (int p = blockIdx.x * 16 + wid; p < P; p += nw) {
        int j  = 4 * p + jj;
        int jm = min(j, N - 1);

        // coalesced row loads: 8 lanes x float4/int4 = 128B per point
        float4 dp = nd4[(unsigned)jm * 8u + sub];
        int4   ip = nid4[(unsigned)jm * 8u + sub];

        __syncwarp();
        *reinterpret_cast<float4*>(&d2_sm[wid][jj][4 * sub]) =
            make_float4(dp.x * dp.x, dp.y * dp.y, dp.z * dp.z, dp.w * dp.w);
        *reinterpret_cast<int4*>(&id_sm[wid][jj][4 * sub]) = ip;
        __syncwarp();

        int lab = labels[jm];
        float4 av = *reinterpret_cast<const float4*>(&a_s[lab][4 * sub]);

        // ---- prologue: issue gathers for k = 0..3 (kp = 0,1) ----
        uint2 vh[2][2];
        {
            int4 id03 = *reinterpret_cast<const int4*>(&id_sm[wid][jj][0]);
            vh[0][0] = gb[(unsigned)id03.x * 8u];
            vh[0][1] = gb[(unsigned)id03.y * 8u];
            vh[1][0] = gb[(unsigned)id03.z * 8u];
            vh[1][1] = gb[(unsigned)id03.w * 8u];
        }

        float acc0 = 0.0f, acc1 = 0.0f, acc2 = 0.0f, acc3 = 0.0f;
        #pragma unroll
        for (int kp = 0; kp < 16; kp++) {
            uint2 u0 = vh[kp & 1][0];     // row for k = 2kp   (4 halves)
            uint2 u1 = vh[kp & 1][1];     // row for k = 2kp+1

            if (kp + 2 < 16) {            // re-issue freed slot for kp+2
                int2 idn = *reinterpret_cast<const int2*>(&id_sm[wid][jj][2 * (kp + 2)]);
                vh[kp & 1][0] = gb[(unsigned)idn.x * 8u];
                vh[kp & 1][1] = gb[(unsigned)idn.y * 8u];
            }

            float2 d2  = *reinterpret_cast<const float2*>(&d2_sm[wid][jj][2 * kp]);
            float4 iv0 = *reinterpret_cast<const float4*>(&ivs_s[2 * kp][sub][0]);
            float4 iv1 = *reinterpret_cast<const float4*>(&ivs_s[2 * kp + 1][sub][0]);

            // k = 2kp
            {
                float2 va = __half22float2(*reinterpret_cast<__half2*>(&u0.x));
                float2 vb = __half22float2(*reinterpret_cast<__half2*>(&u0.y));
                float w0 = fmaxf(fmaf(-d2.x, av.x, 1.0f), 0.0f);
                float w1 = fmaxf(fmaf(-d2.x, av.y, 1.0f), 0.0f);
                float w2 = fmaxf(fmaf(-d2.x, av.z, 1.0f), 0.0f);
                float w3 = fmaxf(fmaf(-d2.x, av.w, 1.0f), 0.0f);
                acc0 = fmaf(va.x * w0, iv0.x, acc0);
                acc1 = fmaf(va.y * w1, iv0.y, acc1);
                acc2 = fmaf(vb.x * w2, iv0.z, acc2);
                acc3 = fmaf(vb.y * w3, iv0.w, acc3);
            }
            // k = 2kp+1
            {
                float2 va = __half22float2(*reinterpret_cast<__half2*>(&u1.x));
                float2 vb = __half22float2(*reinterpret_cast<__half2*>(&u1.y));
                float w0 = fmaxf(fmaf(-d2.y, av.x, 1.0f), 0.0f);
                float w1 = fmaxf(fmaf(-d2.y, av.y, 1.0f), 0.0f);
                float w2 = fmaxf(fmaf(-d2.y, av.z, 1.0f), 0.0f);
                float w3 = fmaxf(fmaf(-d2.y, av.w, 1.0f), 0.0f);
                acc0 = fmaf(va.x * w0, iv1.x, acc0);
                acc1 = fmaf(va.y * w1, iv1.y, acc1);
                acc2 = fmaf(vb.x * w2, iv1.z, acc2);
                acc3 = fmaf(vb.y * w3, iv1.w, acc3);
            }
        }

        float s = (acc0 + acc1) + (acc2 + acc3);
        #pragma unroll
        for (int o = 1; o < 8; o <<= 1)
            s += __shfl_xor_sync(0xffffffffu, s, o);   // reduce over 8-lane group

        if (sub == 0 && j < N) out[j] = s;
    }
}

// ------------------------------------------------------------------
extern "C" void kernel_launch(void* const* d_in, const int* in_sizes, int n_in,
                              void* d_out, int out_size) {
    const float* x       = (const float*)d_in[0];
    const float* enc_w   = (const float*)d_in[1];
    const float* enc_b   = (const float*)d_in[2];
    const float* decoder = (const float*)d_in[3];
    const float* bw_w    = (const float*)d_in[4];
    const float* bw_b    = (const float*)d_in[5];
    const float* nd      = (const float*)d_in[6];
    const int*   nid     = (const int*)d_in[7];
    const int*   labels  = (const int*)d_in[8];
    float* out = (float*)d_out;
    int N = in_sizes[0];

    kA_encoded<<<dim3(16, NCH), 256>>>(enc_w, x, N);
    kB_bandwidths<<<1, NCH * MCL>>>(bw_w, bw_b, enc_b);
    kTB_fused<<<KT_BLOCKS + PB_BLOCKS, 512>>>(decoder, nd, labels, N);
    kPC_output<<<296, 512>>>((const float4*)nd, (const int4*)nid, labels, out, N);
}